// round 2
// baseline (speedup 1.0000x reference)
#include <cuda_runtime.h>
#include <cstddef>

#define NPART 65536
#define NEDGE 524288
#define RIG   4096
#define NF    128

// ---------------- device scratch (no allocations allowed) ----------------
__device__ float g_mean[8];                       // per-dim mean of state[:RIG]
__device__ float g_pbase[(size_t)NPART * NF];     // W_p @ particle_encode + pp_b
__device__ float g_base[(size_t)NEDGE * NF];      // W_r @ relation_encode + rp_b
__device__ float g_A[(size_t)NPART * NF];         // W_re @ effect
__device__ float g_B[(size_t)NPART * NF];         // W_se @ effect
__device__ float g_agg[(size_t)NPART * NF];       // segment sum
__device__ float g_effect[(size_t)NPART * NF];
__device__ float g_vec[NF];                       // pooled sum
__device__ float g_rigid[16];                     // R(9), b(3), c(3)

// ---------------- helpers ----------------
// One 128-wide linear layer: thread `o` owns output channel o.
// Weight row cached in registers, activations read from smem (broadcast LDS.128).
template<bool RELU>
__device__ __forceinline__ void layer128_to(const float* __restrict__ Wrow, float bias,
                                            const float* __restrict__ act,
                                            float* __restrict__ out, int rows, int o)
{
    float w[128];
    const float4* w4 = reinterpret_cast<const float4*>(Wrow);
#pragma unroll
    for (int i = 0; i < 32; i++) {
        float4 t = __ldg(&w4[i]);
        w[4*i+0] = t.x; w[4*i+1] = t.y; w[4*i+2] = t.z; w[4*i+3] = t.w;
    }
    for (int r = 0; r < rows; r++) {
        const float4* a4 = reinterpret_cast<const float4*>(act + r * 128);
        float a0 = bias, a1 = 0.f, a2 = 0.f, a3 = 0.f;
#pragma unroll
        for (int i = 0; i < 32; i++) {
            float4 v = a4[i];
            a0 = fmaf(w[4*i+0], v.x, a0);
            a1 = fmaf(w[4*i+1], v.y, a1);
            a2 = fmaf(w[4*i+2], v.z, a2);
            a3 = fmaf(w[4*i+3], v.w, a3);
        }
        float acc = (a0 + a1) + (a2 + a3);
        out[(size_t)r * 128 + o] = RELU ? fmaxf(acc, 0.f) : acc;
    }
}

// ---------------- kernels ----------------
__global__ void k_mean(const float* __restrict__ state)
{
    __shared__ float s[6];
    if (threadIdx.x < 6) s[threadIdx.x] = 0.f;
    __syncthreads();
    float loc[6] = {0, 0, 0, 0, 0, 0};
    for (int r = threadIdx.x; r < RIG; r += blockDim.x) {
#pragma unroll
        for (int d = 0; d < 6; d++) loc[d] += state[r * 6 + d];
    }
#pragma unroll
    for (int d = 0; d < 6; d++) atomicAdd(&s[d], loc[d]);
    __syncthreads();
    if (threadIdx.x < 6) g_mean[threadIdx.x] = s[threadIdx.x] * (1.f / RIG);
}

// particle encoder (15->128->128) fused with pbase = pp_w[:, :128] @ pe + pp_b
__global__ void k_pe(const float* __restrict__ state, const float* __restrict__ attr,
                     const float* __restrict__ pe_w0, const float* __restrict__ pe_b0,
                     const float* __restrict__ pe_w1, const float* __restrict__ pe_b1,
                     const float* __restrict__ pp_w, const float* __restrict__ pp_b)
{
    __shared__ __align__(16) float s_in[32 * 16];
    __shared__ __align__(16) float s_a[32 * 128];
    __shared__ __align__(16) float s_b[32 * 128];
    int o = threadIdx.x;
    int n0 = blockIdx.x * 32;

    for (int idx = o; idx < 32 * 15; idx += 128) {
        int r = idx / 15, c = idx % 15;
        int n = n0 + r;
        float v;
        if (c < 3)       v = attr[n * 3 + c];
        else if (c < 9)  { int d = c - 3; v = (n < RIG) ? state[n * 6 + d] - g_mean[d] : 0.f; }
        else             v = state[n * 6 + (c - 9)];
        s_in[r * 16 + c] = v;
    }
    __syncthreads();
    // L0: 15 -> 128
    {
        float w[15];
#pragma unroll
        for (int k = 0; k < 15; k++) w[k] = __ldg(&pe_w0[o * 15 + k]);
        float bias = pe_b0[o];
        for (int r = 0; r < 32; r++) {
            float acc = bias;
#pragma unroll
            for (int k = 0; k < 15; k++) acc = fmaf(w[k], s_in[r * 16 + k], acc);
            s_a[r * 128 + o] = fmaxf(acc, 0.f);
        }
    }
    __syncthreads();
    layer128_to<true>(pe_w1 + o * 128, pe_b1[o], s_a, s_b, 32, o);
    __syncthreads();
    // pbase = pp_w[:, :128] @ pe + pp_b  (no relu)
    layer128_to<false>(pp_w + o * 256, pp_b[o], s_b, g_pbase + (size_t)n0 * 128, 32, o);
}

// relation encoder (31->128->128->128) fused with base = rp_w[:, :128] @ relenc + rp_b
__global__ void k_edge(const float* __restrict__ attr, const float* __restrict__ state,
                       const float* __restrict__ Ra,
                       const int* __restrict__ recv, const int* __restrict__ send,
                       const float* __restrict__ re_w0, const float* __restrict__ re_b0,
                       const float* __restrict__ re_w1, const float* __restrict__ re_b1,
                       const float* __restrict__ re_w2, const float* __restrict__ re_b2,
                       const float* __restrict__ rp_w, const float* __restrict__ rp_b)
{
    __shared__ __align__(16) float s_in[32 * 32];
    __shared__ __align__(16) float s_a[32 * 128];
    __shared__ __align__(16) float s_b[32 * 128];
    int o = threadIdx.x;
    int e0 = blockIdx.x * 32;

    for (int idx = o; idx < 32 * 31; idx += 128) {
        int r = idx / 31, c = idx % 31;
        int e = e0 + r;
        float v;
        if (c < 3)       { v = attr[recv[e] * 3 + c]; }
        else if (c < 9)  { int n = recv[e]; int d = c - 3;
                           v = (n < RIG) ? state[n * 6 + d] - g_mean[d] : 0.f; }
        else if (c < 12) { v = attr[send[e] * 3 + (c - 9)]; }
        else if (c < 18) { int n = send[e]; int d = c - 12;
                           v = (n < RIG) ? state[n * 6 + d] - g_mean[d] : 0.f; }
        else if (c < 24) { v = state[recv[e] * 6 + (c - 18)]; }
        else if (c < 30) { v = state[send[e] * 6 + (c - 24)]; }
        else             { v = Ra[e]; }
        s_in[r * 32 + c] = v;
    }
    __syncthreads();
    // L0: 31 -> 128
    {
        float w[31];
#pragma unroll
        for (int k = 0; k < 31; k++) w[k] = __ldg(&re_w0[o * 31 + k]);
        float bias = re_b0[o];
        for (int r = 0; r < 32; r++) {
            float acc = bias;
#pragma unroll
            for (int k = 0; k < 31; k++) acc = fmaf(w[k], s_in[r * 32 + k], acc);
            s_a[r * 128 + o] = fmaxf(acc, 0.f);
        }
    }
    __syncthreads();
    layer128_to<true>(re_w1 + o * 128, re_b1[o], s_a, s_b, 32, o);
    __syncthreads();
    layer128_to<true>(re_w2 + o * 128, re_b2[o], s_b, s_a, 32, o);
    __syncthreads();
    // base = rp_w[:, :128] @ relenc + rp_b   (pre-relu)
    layer128_to<false>(rp_w + o * 384, rp_b[o], s_a, g_base + (size_t)e0 * 128, 32, o);
}

// A = W_re @ effect ; B = W_se @ effect (node-level, cols 128:256 / 256:384 of rp_w)
__global__ void k_prop_node(const float* __restrict__ rp_w)
{
    __shared__ __align__(16) float s_a[32 * 128];
    int o = threadIdx.x;
    int n0 = blockIdx.x * 32;
    for (int idx = o; idx < 32 * 128; idx += 128) s_a[idx] = g_effect[(size_t)n0 * 128 + idx];
    __syncthreads();
    layer128_to<false>(rp_w + o * 384 + 128, 0.f, s_a, g_A + (size_t)n0 * 128, 32, o);
    layer128_to<false>(rp_w + o * 384 + 256, 0.f, s_a, g_B + (size_t)n0 * 128, 32, o);
}

// per-edge: val = relu(base + A[recv] + B[send]); agg[recv] += val (atomics)
template<bool FIRST>
__global__ void k_prop_edge(const int* __restrict__ recv, const int* __restrict__ send)
{
    int gid = blockIdx.x * 256 + threadIdx.x;
    int e = gid >> 5;
    int q = gid & 31;
    int rv = recv[e];
    float4 b4 = *reinterpret_cast<const float4*>(&g_base[(size_t)e * 128 + q * 4]);
    float x = b4.x, y = b4.y, z = b4.z, w = b4.w;
    if (!FIRST) {
        int sd = send[e];
        float4 a4 = *reinterpret_cast<const float4*>(&g_A[(size_t)rv * 128 + q * 4]);
        float4 c4 = *reinterpret_cast<const float4*>(&g_B[(size_t)sd * 128 + q * 4]);
        x += a4.x + c4.x; y += a4.y + c4.y; z += a4.z + c4.z; w += a4.w + c4.w;
    }
    x = fmaxf(x, 0.f); y = fmaxf(y, 0.f); z = fmaxf(z, 0.f); w = fmaxf(w, 0.f);
    float* dst = &g_agg[(size_t)rv * 128 + q * 4];
    atomicAdd(dst + 0, x);
    atomicAdd(dst + 1, y);
    atomicAdd(dst + 2, z);
    atomicAdd(dst + 3, w);
}

// effect = relu(pbase + W_a @ agg) with W_a = pp_w[:, 128:256]
__global__ void k_effect(const float* __restrict__ pp_w)
{
    __shared__ __align__(16) float s_a[32 * 128];
    int o = threadIdx.x;
    int n0 = blockIdx.x * 32;
    for (int idx = o; idx < 32 * 128; idx += 128) s_a[idx] = g_agg[(size_t)n0 * 128 + idx];
    __syncthreads();
    float w[128];
    const float4* w4 = reinterpret_cast<const float4*>(pp_w + o * 256 + 128);
#pragma unroll
    for (int i = 0; i < 32; i++) {
        float4 t = __ldg(&w4[i]);
        w[4*i+0] = t.x; w[4*i+1] = t.y; w[4*i+2] = t.z; w[4*i+3] = t.w;
    }
    for (int r = 0; r < 32; r++) {
        const float4* a4 = reinterpret_cast<const float4*>(&s_a[r * 128]);
        float a0 = g_pbase[(size_t)(n0 + r) * 128 + o], a1 = 0.f, a2 = 0.f, a3 = 0.f;
#pragma unroll
        for (int i = 0; i < 32; i++) {
            float4 v = a4[i];
            a0 = fmaf(w[4*i+0], v.x, a0);
            a1 = fmaf(w[4*i+1], v.y, a1);
            a2 = fmaf(w[4*i+2], v.z, a2);
            a3 = fmaf(w[4*i+3], v.w, a3);
        }
        g_effect[(size_t)(n0 + r) * 128 + o] = fmaxf((a0 + a1) + (a2 + a3), 0.f);
    }
}

// partial sums of effect[:RIG] into g_vec (zeroed before)
__global__ void k_pool()
{
    int o = threadIdx.x;               // 0..127
    int r0 = blockIdx.x * 256;         // 16 blocks x 256 rows
    float s = 0.f;
    for (int r = 0; r < 256; r++) s += g_effect[(size_t)(r0 + r) * 128 + o];
    atomicAdd(&g_vec[o], s);
}

__global__ void k_rigid(const float* __restrict__ rg_w0, const float* __restrict__ rg_b0,
                        const float* __restrict__ rg_w1, const float* __restrict__ rg_b1,
                        const float* __restrict__ rg_w2, const float* __restrict__ rg_b2)
{
    __shared__ float p[128], h[128], t7[8];
    int o = threadIdx.x;
    p[o] = g_vec[o] * (1.f / RIG);
    __syncthreads();
    {
        float acc = rg_b0[o];
        for (int k = 0; k < 128; k++) acc = fmaf(rg_w0[o * 128 + k], p[k], acc);
        h[o] = fmaxf(acc, 0.f);
    }
    __syncthreads();
    {
        float acc = rg_b1[o];
        for (int k = 0; k < 128; k++) acc = fmaf(rg_w1[o * 128 + k], h[k], acc);
        p[o] = fmaxf(acc, 0.f);
    }
    __syncthreads();
    if (o < 7) {
        float acc = rg_b2[o];
        for (int k = 0; k < 128; k++) acc = fmaf(rg_w2[o * 128 + k], p[k], acc);
        t7[o] = acc;
    }
    __syncthreads();
    if (o == 0) {
        float t0 = t7[0], t1 = t7[1], t2 = t7[2], t3 = t7[3];
        float inv = rsqrtf(t0 * t0 + t1 * t1 + t2 * t2 + t3 * t3);
        float w = t0 * inv, x = t1 * inv, y = t2 * inv, z = t3 * inv;
        // R rows as in reference
        g_rigid[0] = 1.f - 2.f * (y * y + z * z);
        g_rigid[1] = 2.f * (x * y + z * w);
        g_rigid[2] = 2.f * (x * z - y * w);
        g_rigid[3] = 2.f * (x * y - z * w);
        g_rigid[4] = 1.f - 2.f * (x * x + z * z);
        g_rigid[5] = 2.f * (y * z + x * w);
        g_rigid[6] = 2.f * (x * z + y * w);
        g_rigid[7] = 2.f * (y * z - x * w);
        g_rigid[8] = 1.f - 2.f * (x * x + y * y);
        g_rigid[9]  = t7[4]; g_rigid[10] = t7[5]; g_rigid[11] = t7[6];
        g_rigid[12] = g_mean[0]; g_rigid[13] = g_mean[1]; g_rigid[14] = g_mean[2];
    }
}

__global__ void k_out_rigid(const float* __restrict__ state, float* __restrict__ out)
{
    int i = blockIdx.x * 256 + threadIdx.x;   // < RIG
    float R0 = g_rigid[0], R1 = g_rigid[1], R2 = g_rigid[2];
    float R3 = g_rigid[3], R4 = g_rigid[4], R5 = g_rigid[5];
    float R6 = g_rigid[6], R7 = g_rigid[7], R8 = g_rigid[8];
    float bx = g_rigid[9], by = g_rigid[10], bz = g_rigid[11];
    float cx = g_rigid[12], cy = g_rigid[13], cz = g_rigid[14];
    float p0x = state[i * 6 + 0], p0y = state[i * 6 + 1], p0z = state[i * 6 + 2];
    float dx = p0x - cx, dy = p0y - cy, dz = p0z - cz;
    float p1x = dx * R0 + dy * R3 + dz * R6 + bx + cx;
    float p1y = dx * R1 + dy * R4 + dz * R7 + by + cy;
    float p1z = dx * R2 + dy * R5 + dz * R8 + bz + cz;
    out[i * 3 + 0] = (p1x - p0x) * 60.f;
    out[i * 3 + 1] = (p1y - p0y) * 60.f;
    out[i * 3 + 2] = (p1z - p0z) * 60.f;
}

__global__ void k_fluid(const float* __restrict__ fl_w0, const float* __restrict__ fl_b0,
                        const float* __restrict__ fl_w1, const float* __restrict__ fl_b1,
                        const float* __restrict__ fl_w2, const float* __restrict__ fl_b2,
                        float* __restrict__ out)
{
    __shared__ __align__(16) float s_a[32 * 128];
    __shared__ __align__(16) float s_b[32 * 128];
    int o = threadIdx.x;
    int n0 = RIG + blockIdx.x * 32;
    for (int idx = o; idx < 32 * 128; idx += 128) s_a[idx] = g_effect[(size_t)n0 * 128 + idx];
    __syncthreads();
    layer128_to<true>(fl_w0 + o * 128, fl_b0[o], s_a, s_b, 32, o);
    __syncthreads();
    layer128_to<true>(fl_w1 + o * 128, fl_b1[o], s_b, s_a, 32, o);
    __syncthreads();
    if (o < 96) {
        int r = o / 3, j = o % 3;
        float acc = fl_b2[j];
        const float* a = &s_a[r * 128];
        for (int k = 0; k < 128; k++) acc = fmaf(__ldg(&fl_w2[j * 128 + k]), a[k], acc);
        out[(size_t)(n0 + r) * 3 + j] = acc;
    }
}

// ---------------- launch ----------------
extern "C" void kernel_launch(void* const* d_in, const int* in_sizes, int n_in,
                              void* d_out, int out_size)
{
    const float* state  = (const float*)d_in[0];
    const float* attr   = (const float*)d_in[1];
    const float* Ra     = (const float*)d_in[2];
    const int*   recv   = (const int*)d_in[3];
    const int*   send   = (const int*)d_in[4];
    const float* pe_w0  = (const float*)d_in[5];
    const float* pe_b0  = (const float*)d_in[6];
    const float* pe_w1  = (const float*)d_in[7];
    const float* pe_b1  = (const float*)d_in[8];
    const float* re_w0  = (const float*)d_in[9];
    const float* re_b0  = (const float*)d_in[10];
    const float* re_w1  = (const float*)d_in[11];
    const float* re_b1  = (const float*)d_in[12];
    const float* re_w2  = (const float*)d_in[13];
    const float* re_b2  = (const float*)d_in[14];
    const float* rp_w   = (const float*)d_in[15];
    const float* rp_b   = (const float*)d_in[16];
    const float* pp_w   = (const float*)d_in[17];
    const float* pp_b   = (const float*)d_in[18];
    const float* rg_w0  = (const float*)d_in[19];
    const float* rg_b0  = (const float*)d_in[20];
    const float* rg_w1  = (const float*)d_in[21];
    const float* rg_b1  = (const float*)d_in[22];
    const float* rg_w2  = (const float*)d_in[23];
    const float* rg_b2  = (const float*)d_in[24];
    const float* fl_w0  = (const float*)d_in[25];
    const float* fl_b0  = (const float*)d_in[26];
    const float* fl_w1  = (const float*)d_in[27];
    const float* fl_b1  = (const float*)d_in[28];
    const float* fl_w2  = (const float*)d_in[29];
    const float* fl_b2  = (const float*)d_in[30];
    float* out = (float*)d_out;

    void* p_agg = nullptr; void* p_vec = nullptr;
    cudaGetSymbolAddress(&p_agg, g_agg);
    cudaGetSymbolAddress(&p_vec, g_vec);

    k_mean<<<1, 256>>>(state);
    k_pe<<<NPART / 32, 128>>>(state, attr, pe_w0, pe_b0, pe_w1, pe_b1, pp_w, pp_b);
    k_edge<<<NEDGE / 32, 128>>>(attr, state, Ra, recv, send,
                                re_w0, re_b0, re_w1, re_b1, re_w2, re_b2, rp_w, rp_b);

    // propagation step 1 (effect == 0 -> rel_eff = relu(base))
    cudaMemsetAsync(p_agg, 0, (size_t)NPART * NF * sizeof(float));
    k_prop_edge<true><<<NEDGE * 32 / 256, 256>>>(recv, send);
    k_effect<<<NPART / 32, 128>>>(pp_w);

    // propagation step 2
    k_prop_node<<<NPART / 32, 128>>>(rp_w);
    cudaMemsetAsync(p_agg, 0, (size_t)NPART * NF * sizeof(float));
    k_prop_edge<false><<<NEDGE * 32 / 256, 256>>>(recv, send);
    k_effect<<<NPART / 32, 128>>>(pp_w);

    // heads
    cudaMemsetAsync(p_vec, 0, NF * sizeof(float));
    k_pool<<<16, 128>>>();
    k_rigid<<<1, 128>>>(rg_w0, rg_b0, rg_w1, rg_b1, rg_w2, rg_b2);
    k_out_rigid<<<RIG / 256, 256>>>(state, out);
    k_fluid<<<(NPART - RIG) / 32, 128>>>(fl_w0, fl_b0, fl_w1, fl_b1, fl_w2, fl_b2, out);
}